// round 11
// baseline (speedup 1.0000x reference)
#include <cuda_runtime.h>
#include <cstdint>

#define Bn 64
#define Tn 2048
#define In 128
#define Hn 256
#define THREADS 512
#define PT 256
#define NCOL 16
#define NBAT 8
#define NCG  16
#define NBG  8
#define GCTA 128
#define KA 384
#define KB 512
#define RS 6

typedef unsigned long long u64;
typedef uint32_t u32;

// ---------------- device scratch ----------------
__device__ __align__(256) u64   g_xT2[(size_t)Tn * In * Bn];  // x dup'd {v,v}: [t][k][b]
__device__ __align__(256) float g_h0[2 * Hn * Bn];            // [buf][k][b]
__device__ __align__(256) float g_h1[2 * Hn * Bn];
// doorbell step-stamps: [bg][producer][consumer][32] (128B-spaced private lines)
__device__ __align__(128) unsigned g_dbA[NBG * 16 * 16 * 32];
__device__ __align__(128) unsigned g_dbB[NBG * 16 * 16 * 32];

// ---------------- packed f32x2 helpers ----------------
__device__ __forceinline__ void fma2(u64 &d, u64 a, u64 b) {
    asm("fma.rn.f32x2 %0, %1, %2, %0;" : "+l"(d) : "l"(a), "l"(b));
}
__device__ __forceinline__ u64 add2(u64 a, u64 b) {
    u64 d; asm("add.rn.f32x2 %0, %1, %2;" : "=l"(d) : "l"(a), "l"(b)); return d;
}
__device__ __forceinline__ u64 dup2(float f) {
    u64 d; asm("mov.b64 %0, {%1, %1};" : "=l"(d) : "f"(f)); return d;
}
__device__ __forceinline__ u64 pack2(float lo, float hi) {
    u64 d; asm("mov.b64 %0, {%1, %2};" : "=l"(d) : "f"(lo), "f"(hi)); return d;
}
__device__ __forceinline__ float lo2(u64 v) { return __uint_as_float((unsigned)(v & 0xffffffffull)); }
__device__ __forceinline__ float hi2(u64 v) { return __uint_as_float((unsigned)(v >> 32)); }

__device__ __forceinline__ void ldcg2(const u64* p, u64 &a, u64 &b) {
    asm volatile("ld.global.cg.v2.u64 {%0, %1}, [%2];" : "=l"(a), "=l"(b) : "l"(p));
}
__device__ __forceinline__ float4 ldcgf4(const float* p) {
    float4 v;
    asm volatile("ld.global.cg.v4.f32 {%0, %1, %2, %3}, [%4];"
                 : "=f"(v.x), "=f"(v.y), "=f"(v.z), "=f"(v.w) : "l"(p));
    return v;
}
__device__ __forceinline__ void stcgf(float* p, float v) {
    asm volatile("st.global.cg.f32 [%0], %1;" :: "l"(p), "f"(v) : "memory");
}

// doorbell ops: private line per (producer, consumer)
__device__ __forceinline__ void db_poll(const unsigned* p, int tgt) {
    if (tgt <= 0) return;
    int v;
    do { asm volatile("ld.acquire.gpu.global.u32 %0, [%1];" : "=r"(v) : "l"(p) : "memory"); }
    while (v < tgt);
}
__device__ __forceinline__ void db_write_row(unsigned* rowbase, int val) {
#pragma unroll
    for (int j = 0; j < 16; j++)
        asm volatile("st.release.gpu.global.u32 [%0], %1;"
                     :: "l"(rowbase + j * 32), "r"(val) : "memory");
}
__device__ __forceinline__ void s_poll(volatile unsigned* c, int tgt) {
    if (tgt <= 0) return;
    while ((int)(*c) < tgt) { }
    __threadfence_block();
}
__device__ __forceinline__ void nbar(int id) {
    asm volatile("bar.sync %0, 256;" :: "r"(id) : "memory");
}

// fused blend: h' = sg(a)*tanh(c) + (1-sg(a))*hp  (2 ex2 + 1 div)
__device__ __forceinline__ float blend(u64 acc, float hp) {
    float cnd = fmaxf(lo2(acc), -15.0f);
    float alp = fmaxf(hi2(acc), -30.0f);
    float v = __expf(-2.0f * cnd);
    float u = __expf(-alp);
    float t2 = 1.0f + v;
    float num = __fmaf_rn(u * hp, t2, 1.0f - v);
    float den = (1.0f + u) * t2;
    return __fdividef(num, den);
}

// ---------------- prep ----------------
__global__ void prep_kernel(const float* __restrict__ x) {
    __shared__ float s[In][65];
    const int t = blockIdx.x;
    const int tid = threadIdx.x;
    for (int idx = tid; idx < Bn * In; idx += PT) {
        int b = idx >> 7, i = idx & (In - 1);
        s[i][b] = x[((size_t)b * Tn + t) * In + i];
    }
    __syncthreads();
    for (int idx = tid; idx < In * Bn; idx += PT) {
        int i = idx >> 6, b = idx & (Bn - 1);
        g_xT2[((size_t)t * In + i) * Bn + b] = dup2(s[i][b]);
    }
    if (t == 0) {
        for (int i = tid; i < NBG * 16 * 16; i += PT) {
            g_dbA[i * 32] = 0u;
            g_dbB[i * 32] = 0u;
        }
    }
    if (t < 2) {
        for (int i = tid; i < Hn * Bn; i += PT) {
            g_h0[t * Hn * Bn + i] = 0.0f;
            g_h1[t * Hn * Bn + i] = 0.0f;
        }
    }
}

// ---------------- persistent pipelined RNN kernel ----------------
__global__ void __launch_bounds__(THREADS, 1) rnn_kernel(
    const float* __restrict__ Wih0, const float* __restrict__ Whh0,
    const float* __restrict__ bh0,  const float* __restrict__ Wax0,
    const float* __restrict__ Wah0, const float* __restrict__ ba0,
    const float* __restrict__ Wih1, const float* __restrict__ Whh1,
    const float* __restrict__ bh1,  const float* __restrict__ Wax1,
    const float* __restrict__ Wah1, const float* __restrict__ ba1,
    float* __restrict__ out)
{
    extern __shared__ u64 sm[];
    u64* wAs   = sm;                       // [KA][16]
    u64* wBs   = wAs + KA * NCOL;          // [KB][16]
    u64* sh0   = wBs + KB * NCOL;          // [2][Hn][NBAT] dup'd
    u64* sh1   = sh0 + 2 * Hn * NBAT;      // [Hn][NBAT] dup'd
    u64* redA  = sh1 + Hn * NBAT;          // [256][RS]
    u64* redB  = redA + 256 * RS;          // [256][RS]
    u64* biasA = redB + 256 * RS;          // [16]
    u64* biasB = biasA + NCOL;             // [16]
    __shared__ unsigned s_aStage, s_bDone;

    const int tid  = threadIdx.x;
    const int cg   = blockIdx.x & (NCG - 1);
    const int bg   = blockIdx.x >> 4;
    const int col0 = cg * NCOL;
    const int b0g  = bg * NBAT;

    unsigned* dbA_base = g_dbA + (size_t)bg * 16 * 16 * 32;
    unsigned* dbB_base = g_dbB + (size_t)bg * 16 * 16 * 32;
    unsigned* dbA_prow = dbA_base + (size_t)cg * 16 * 32;   // my producer row (A)
    unsigned* dbB_prow = dbB_base + (size_t)cg * 16 * 32;   // my producer row (B)

    for (int idx = tid; idx < KA * NCOL; idx += THREADS) {
        int k = idx >> 4, c = idx & 15, C = col0 + c;
        float wc = (k < In) ? Wih0[k * Hn + C] : Whh0[(k - In) * Hn + C];
        float wa = (k < In) ? Wax0[k * Hn + C] : Wah0[(k - In) * Hn + C];
        wAs[idx] = pack2(wc, wa);
    }
    for (int idx = tid; idx < KB * NCOL; idx += THREADS) {
        int k = idx >> 4, c = idx & 15, C = col0 + c;
        float wc = (k < Hn) ? Wih1[k * Hn + C] : Whh1[(k - Hn) * Hn + C];
        float wa = (k < Hn) ? Wax1[k * Hn + C] : Wah1[(k - Hn) * Hn + C];
        wBs[idx] = pack2(wc, wa);
    }
    if (tid < NCOL) {
        biasA[tid] = pack2(bh0[col0 + tid], ba0[col0 + tid]);
        biasB[tid] = pack2(bh1[col0 + tid], ba1[col0 + tid]);
    }
    if (tid == 0) { s_aStage = 0u; s_bDone = 0u; }
    __syncthreads();

    const size_t OFF = (size_t)Bn * Tn * Hn;

    if (tid >= 256) {
        // ================= A-engine (warps 8-15) =================
        const int atid = tid - 256;
        const int w  = atid >> 5, ln = atid & 31;
        const int bp = ln >> 3,  cp = ln & 7;
        const int b0 = b0g + bp * 2;
        // epilogue cell map: rb minor (coalesced h-state stores)
        const int rb = atid & 7, rc = atid >> 3;           // valid for atid<128
        const int ridx = (rb >> 1) * 8 + (rc >> 1);
        const int raid = (rb & 1) * 2 + (rc & 1);
        const int C = col0 + rc, B = b0g + rb;
        // my staging row's producer line
        const unsigned* myA_line = dbA_base + (size_t)(atid >> 4) * 16 * 32 + (size_t)cg * 32;
        float hprev = 0.0f;

        for (int s = 0; s <= Tn; s++) {
            const bool full = (s < Tn);
            u64 a00 = 0, a01 = 0, a10 = 0, a11 = 0;

            if (full) {  // x-part: fills the wait shadow
                const u64* xp = g_xT2 + ((size_t)s * In + w * 16) * Bn + b0;
                const u64* wp = wAs + (w * 16) * NCOL + cp * 2;
#pragma unroll
                for (int i = 0; i < 16; i++) {
                    u64 s0, s1; ldcg2(xp + (size_t)i * Bn, s0, s1);
                    ulonglong2 wv = *(const ulonglong2*)(wp + i * NCOL);
                    fma2(a00, s0, wv.x); fma2(a01, s0, wv.y);
                    fma2(a10, s1, wv.x); fma2(a11, s1, wv.y);
                }
            }
            s_poll(&s_bDone, s - 2);              // sh0[s&1] free
            db_poll(myA_line, s);                 // my row's producer done A(s-1)

            {   // stage row atid of h0[s-1] (dup'd)
                const float* src = g_h0 + ((((s + 1) & 1)) * Hn + atid) * Bn + b0g;
                float4 v0 = ldcgf4(src);
                float4 v1 = ldcgf4(src + 4);
                u64* d = sh0 + (((s & 1)) * Hn + atid) * NBAT;
                *(ulonglong2*)(d)     = make_ulonglong2(dup2(v0.x), dup2(v0.y));
                *(ulonglong2*)(d + 2) = make_ulonglong2(dup2(v0.z), dup2(v0.w));
                *(ulonglong2*)(d + 4) = make_ulonglong2(dup2(v1.x), dup2(v1.y));
                *(ulonglong2*)(d + 6) = make_ulonglong2(dup2(v1.z), dup2(v1.w));
            }
            nbar(1);
            if (atid == 0) atomicAdd_block(&s_aStage, 1u);

            if (full) {
                const u64* sp = sh0 + (((s & 1)) * Hn + w * 32) * NBAT + bp * 2;
                const u64* wp = wAs + (In + w * 32) * NCOL + cp * 2;
#pragma unroll 8
                for (int i = 0; i < 32; i++) {
                    ulonglong2 sv = *(const ulonglong2*)(sp + i * NBAT);
                    ulonglong2 wv = *(const ulonglong2*)(wp + i * NCOL);
                    fma2(a00, sv.x, wv.x); fma2(a01, sv.x, wv.y);
                    fma2(a10, sv.y, wv.x); fma2(a11, sv.y, wv.y);
                }
                u64* rr = redA + atid * RS;
                *(ulonglong2*)(rr)     = make_ulonglong2(a00, a01);
                *(ulonglong2*)(rr + 2) = make_ulonglong2(a10, a11);
                nbar(1);
                if (atid < 128) {
                    u64 acc = biasA[rc];
#pragma unroll
                    for (int ww = 0; ww < 8; ww++)
                        acc = add2(acc, redA[(ww * 32 + ridx) * RS + raid]);
                    float hn = blend(acc, hprev);
                    hprev = hn;
                    stcgf(&g_h0[((s & 1) * Hn + C) * Bn + B], hn);   // 128B-coalesced groups
                }
                nbar(1);
                if (atid == 0) db_write_row(dbA_prow, s + 1);
            }
        }
        if (atid < 128) out[OFF + (size_t)B * Hn + C] = hprev;

    } else {
        // ================= B-engine (warps 0-7) =================
        const int btid = tid;
        const int w  = btid >> 5, ln = btid & 31;
        const int bp = ln >> 3,  cp = ln & 7;
        const int rb = btid & 7, rc = btid >> 3;           // valid for btid<128
        const int ridx = (rb >> 1) * 8 + (rc >> 1);
        const int raid = (rb & 1) * 2 + (rc & 1);
        const int C = col0 + rc, B = b0g + rb;
        const unsigned* myB_line = dbB_base + (size_t)(btid >> 4) * 16 * 32 + (size_t)cg * 32;
        float hprev = 0.0f;

        for (int t = 0; t < Tn; t++) {
            s_poll(&s_aStage, t + 2);             // h0[t] staged in sh0[(t+1)&1]
            db_poll(myB_line, t);                 // my row's producer done B(t-1)

            {   // stage row btid of h1[t-1]
                const float* src = g_h1 + ((((t + 1) & 1)) * Hn + btid) * Bn + b0g;
                float4 v0 = ldcgf4(src);
                float4 v1 = ldcgf4(src + 4);
                u64* d = sh1 + btid * NBAT;
                *(ulonglong2*)(d)     = make_ulonglong2(dup2(v0.x), dup2(v0.y));
                *(ulonglong2*)(d + 2) = make_ulonglong2(dup2(v0.z), dup2(v0.w));
                *(ulonglong2*)(d + 4) = make_ulonglong2(dup2(v1.x), dup2(v1.y));
                *(ulonglong2*)(d + 6) = make_ulonglong2(dup2(v1.z), dup2(v1.w));
            }
            nbar(2);

            u64 a00 = 0, a01 = 0, a10 = 0, a11 = 0;
            {
                const int p0 = (t + 1) & 1;
                const u64* s0 = sh0 + (p0 * Hn + w * 32) * NBAT + bp * 2;
                const u64* w1 = wBs + (w * 32) * NCOL + cp * 2;
                const u64* s1 = sh1 + (w * 32) * NBAT + bp * 2;
                const u64* w2 = wBs + (Hn + w * 32) * NCOL + cp * 2;
#pragma unroll 8
                for (int i = 0; i < 32; i++) {
                    ulonglong2 sv = *(const ulonglong2*)(s0 + i * NBAT);
                    ulonglong2 wv = *(const ulonglong2*)(w1 + i * NCOL);
                    fma2(a00, sv.x, wv.x); fma2(a01, sv.x, wv.y);
                    fma2(a10, sv.y, wv.x); fma2(a11, sv.y, wv.y);
                    sv = *(const ulonglong2*)(s1 + i * NBAT);
                    wv = *(const ulonglong2*)(w2 + i * NCOL);
                    fma2(a00, sv.x, wv.x); fma2(a01, sv.x, wv.y);
                    fma2(a10, sv.y, wv.x); fma2(a11, sv.y, wv.y);
                }
            }
            {
                u64* rr = redB + btid * RS;
                *(ulonglong2*)(rr)     = make_ulonglong2(a00, a01);
                *(ulonglong2*)(rr + 2) = make_ulonglong2(a10, a11);
            }
            nbar(2);
            if (btid == 0) atomicAdd_block(&s_bDone, 1u);

            if (btid < 128) {
                u64 acc = biasB[rc];
#pragma unroll
                for (int ww = 0; ww < 8; ww++)
                    acc = add2(acc, redB[(ww * 32 + ridx) * RS + raid]);
                float hn = blend(acc, hprev);
                hprev = hn;
                stcgf(&g_h1[((t & 1) * Hn + C) * Bn + B], hn);
                out[((size_t)B * Tn + t) * Hn + C] = hn;
            }
            nbar(2);
            if (btid == 0) db_write_row(dbB_prow, t + 1);
        }
        if (btid < 128) out[OFF + (size_t)Bn * Hn + (size_t)B * Hn + C] = hprev;
    }
}

// ---------------- launch ----------------
extern "C" void kernel_launch(void* const* d_in, const int* in_sizes, int n_in,
                              void* d_out, int out_size) {
    const float* x    = (const float*)d_in[0];
    const float* Wih0 = (const float*)d_in[1];
    const float* Whh0 = (const float*)d_in[2];
    const float* bh0  = (const float*)d_in[3];
    const float* Wax0 = (const float*)d_in[4];
    const float* Wah0 = (const float*)d_in[5];
    const float* ba0  = (const float*)d_in[6];
    const float* Wih1 = (const float*)d_in[7];
    const float* Whh1 = (const float*)d_in[8];
    const float* bh1  = (const float*)d_in[9];
    const float* Wax1 = (const float*)d_in[10];
    const float* Wah1 = (const float*)d_in[11];
    const float* ba1  = (const float*)d_in[12];
    float* out = (float*)d_out;

    const int smem = (KA * NCOL + KB * NCOL
                    + 2 * Hn * NBAT + Hn * NBAT
                    + 2 * 256 * RS
                    + 2 * NCOL) * 8;
    cudaFuncSetAttribute(rnn_kernel, cudaFuncAttributeMaxDynamicSharedMemorySize, smem);

    prep_kernel<<<Tn, PT>>>(x);
    rnn_kernel<<<GCTA, THREADS, smem>>>(
        Wih0, Whh0, bh0, Wax0, Wah0, ba0,
        Wih1, Whh1, bh1, Wax1, Wah1, ba1,
        out);
}

// round 12
// speedup vs baseline: 2.3549x; 2.3549x over previous
#include <cuda_runtime.h>
#include <cstdint>

#define Bn 64
#define Tn 2048
#define In 128
#define Hn 256
#define THREADS 512
#define PT 256
#define NCOL 16
#define NBAT 8
#define NCG  16
#define NBG  8
#define GCTA 128
#define KA 384
#define KB 512
#define RS 6

typedef unsigned long long u64;
typedef uint32_t u32;

// ---------------- device scratch ----------------
__device__ __align__(256) u64   g_xT2[(size_t)Tn * In * Bn];  // x dup'd {v,v}: [t][k][b]
__device__ __align__(256) float g_h0[2 * Hn * Bn];            // [buf][k][b]
__device__ __align__(256) float g_h1[2 * Hn * Bn];
__device__ __align__(128) unsigned g_ctrA[NBG * 32];
__device__ __align__(128) unsigned g_ctrB[NBG * 32];

// ---------------- packed f32x2 helpers ----------------
__device__ __forceinline__ void fma2(u64 &d, u64 a, u64 b) {
    asm("fma.rn.f32x2 %0, %1, %2, %0;" : "+l"(d) : "l"(a), "l"(b));
}
__device__ __forceinline__ u64 add2(u64 a, u64 b) {
    u64 d; asm("add.rn.f32x2 %0, %1, %2;" : "=l"(d) : "l"(a), "l"(b)); return d;
}
__device__ __forceinline__ u64 dup2(float f) {
    u64 d; asm("mov.b64 %0, {%1, %1};" : "=l"(d) : "f"(f)); return d;
}
__device__ __forceinline__ u64 pack2(float lo, float hi) {
    u64 d; asm("mov.b64 %0, {%1, %2};" : "=l"(d) : "f"(lo), "f"(hi)); return d;
}
__device__ __forceinline__ float lo2(u64 v) { return __uint_as_float((unsigned)(v & 0xffffffffull)); }
__device__ __forceinline__ float hi2(u64 v) { return __uint_as_float((unsigned)(v >> 32)); }

__device__ __forceinline__ void ldcg2(const u64* p, u64 &a, u64 &b) {
    asm volatile("ld.global.cg.v2.u64 {%0, %1}, [%2];" : "=l"(a), "=l"(b) : "l"(p));
}
__device__ __forceinline__ float4 ldcgf4(const float* p) {
    float4 v;
    asm volatile("ld.global.cg.v4.f32 {%0, %1, %2, %3}, [%4];"
                 : "=f"(v.x), "=f"(v.y), "=f"(v.z), "=f"(v.w) : "l"(p));
    return v;
}
__device__ __forceinline__ void stcgf(float* p, float v) {
    asm volatile("st.global.cg.f32 [%0], %1;" :: "l"(p), "f"(v) : "memory");
}

__device__ __forceinline__ void g_arrive(unsigned* c) {
    unsigned old;
    asm volatile("atom.release.gpu.global.add.u32 %0, [%1], 1;" : "=r"(old) : "l"(c) : "memory");
}
// lane0-only spin, broadcast, single acquire per thread
__device__ __forceinline__ void g_poll_w(unsigned* c, int tgt) {
    if (tgt <= 0) return;
    if ((threadIdx.x & 31) == 0) {
        int v;
        do { asm volatile("ld.acquire.gpu.global.u32 %0, [%1];" : "=r"(v) : "l"(c) : "memory"); }
        while (v < tgt);
    }
    __syncwarp();
    int v2;
    asm volatile("ld.acquire.gpu.global.u32 %0, [%1];" : "=r"(v2) : "l"(c) : "memory");
}
// smem mailbox: lane0-only spin
__device__ __forceinline__ void s_poll_w(volatile unsigned* c, int tgt) {
    if (tgt <= 0) return;
    if ((threadIdx.x & 31) == 0) {
        while ((int)(*c) < tgt) { }
    }
    __syncwarp();
    __threadfence_block();
}
__device__ __forceinline__ void nbar(int id) {
    asm volatile("bar.sync %0, 256;" :: "r"(id) : "memory");
}

// fused blend: h' = sg(a)*tanh(c) + (1-sg(a))*hp  (2 ex2 + 1 div)
__device__ __forceinline__ float blend(u64 acc, float hp) {
    float cnd = fmaxf(lo2(acc), -15.0f);
    float alp = fmaxf(hi2(acc), -30.0f);
    float v = __expf(-2.0f * cnd);
    float u = __expf(-alp);
    float t2 = 1.0f + v;
    float num = __fmaf_rn(u * hp, t2, 1.0f - v);
    float den = (1.0f + u) * t2;
    return __fdividef(num, den);
}

// ---------------- prep ----------------
__global__ void prep_kernel(const float* __restrict__ x) {
    __shared__ float s[In][65];
    const int t = blockIdx.x;
    const int tid = threadIdx.x;
    for (int idx = tid; idx < Bn * In; idx += PT) {
        int b = idx >> 7, i = idx & (In - 1);
        s[i][b] = x[((size_t)b * Tn + t) * In + i];
    }
    __syncthreads();
    for (int idx = tid; idx < In * Bn; idx += PT) {
        int i = idx >> 6, b = idx & (Bn - 1);
        g_xT2[((size_t)t * In + i) * Bn + b] = dup2(s[i][b]);
    }
    if (t == 0 && tid < NBG) { g_ctrA[tid * 32] = 0u; g_ctrB[tid * 32] = 0u; }
    if (t < 2) {
        for (int i = tid; i < Hn * Bn; i += PT) {
            g_h0[t * Hn * Bn + i] = 0.0f;
            g_h1[t * Hn * Bn + i] = 0.0f;
        }
    }
}

// ---------------- persistent pipelined RNN kernel ----------------
__global__ void __launch_bounds__(THREADS, 1) rnn_kernel(
    const float* __restrict__ Wih0, const float* __restrict__ Whh0,
    const float* __restrict__ bh0,  const float* __restrict__ Wax0,
    const float* __restrict__ Wah0, const float* __restrict__ ba0,
    const float* __restrict__ Wih1, const float* __restrict__ Whh1,
    const float* __restrict__ bh1,  const float* __restrict__ Wax1,
    const float* __restrict__ Wah1, const float* __restrict__ ba1,
    float* __restrict__ out)
{
    extern __shared__ u64 sm[];
    u64* wAs   = sm;                       // [KA][16]
    u64* wBs   = wAs + KA * NCOL;          // [KB][16]
    u64* sh0   = wBs + KB * NCOL;          // [2][Hn][NBAT] dup'd
    u64* sh1   = sh0 + 2 * Hn * NBAT;      // [Hn][NBAT] dup'd
    u64* redA  = sh1 + Hn * NBAT;          // [256][RS]
    u64* redB  = redA + 256 * RS;          // [256][RS]
    u64* biasA = redB + 256 * RS;          // [16]
    u64* biasB = biasA + NCOL;             // [16]
    __shared__ unsigned s_aStage, s_bDone;

    const int tid  = threadIdx.x;
    const int cg   = blockIdx.x & (NCG - 1);
    const int bg   = blockIdx.x >> 4;
    const int col0 = cg * NCOL;
    const int b0g  = bg * NBAT;
    unsigned* ctrA = &g_ctrA[bg * 32];
    unsigned* ctrB = &g_ctrB[bg * 32];

    for (int idx = tid; idx < KA * NCOL; idx += THREADS) {
        int k = idx >> 4, c = idx & 15, C = col0 + c;
        float wc = (k < In) ? Wih0[k * Hn + C] : Whh0[(k - In) * Hn + C];
        float wa = (k < In) ? Wax0[k * Hn + C] : Wah0[(k - In) * Hn + C];
        wAs[idx] = pack2(wc, wa);
    }
    for (int idx = tid; idx < KB * NCOL; idx += THREADS) {
        int k = idx >> 4, c = idx & 15, C = col0 + c;
        float wc = (k < Hn) ? Wih1[k * Hn + C] : Whh1[(k - Hn) * Hn + C];
        float wa = (k < Hn) ? Wax1[k * Hn + C] : Wah1[(k - Hn) * Hn + C];
        wBs[idx] = pack2(wc, wa);
    }
    if (tid < NCOL) {
        biasA[tid] = pack2(bh0[col0 + tid], ba0[col0 + tid]);
        biasB[tid] = pack2(bh1[col0 + tid], ba1[col0 + tid]);
    }
    if (tid == 0) { s_aStage = 0u; s_bDone = 0u; }
    __syncthreads();

    const size_t OFF = (size_t)Bn * Tn * Hn;

    if (tid >= 256) {
        // ================= A-engine (warps 8-15) =================
        const int atid = tid - 256;
        const int w  = atid >> 5, ln = atid & 31;
        const int bp = ln >> 3,  cp = ln & 7;
        const int b0 = b0g + bp * 2;
        // batch-minor epilogue map: coalesced h0 state stores (16 sectors)
        const int rb = atid & 7, rc = atid >> 3;           // valid for atid<128
        const int ridx = (rb >> 1) * 8 + (rc >> 1);
        const int raid = (rb & 1) * 2 + (rc & 1);
        const int C = col0 + rc, B = b0g + rb;
        float hprev = 0.0f;

        for (int s = 0; s <= Tn; s++) {
            const bool full = (s < Tn);
            u64 a00 = 0, a01 = 0, a10 = 0, a11 = 0;

            if (full) {  // x-part fills the wait shadow
                const u64* xp = g_xT2 + ((size_t)s * In + w * 16) * Bn + b0;
                const u64* wp = wAs + (w * 16) * NCOL + cp * 2;
#pragma unroll
                for (int i = 0; i < 16; i++) {
                    u64 s0, s1; ldcg2(xp + (size_t)i * Bn, s0, s1);
                    ulonglong2 wv = *(const ulonglong2*)(wp + i * NCOL);
                    fma2(a00, s0, wv.x); fma2(a01, s0, wv.y);
                    fma2(a10, s1, wv.x); fma2(a11, s1, wv.y);
                }
            }
            s_poll_w(&s_bDone, s - 2);        // sh0[s&1] free
            g_poll_w(ctrA, 16 * s);           // h0[s-1] visible

            {   // stage row atid of h0[s-1] (dup'd)
                const float* src = g_h0 + ((((s + 1) & 1)) * Hn + atid) * Bn + b0g;
                float4 v0 = ldcgf4(src);
                float4 v1 = ldcgf4(src + 4);
                u64* d = sh0 + (((s & 1)) * Hn + atid) * NBAT;
                *(ulonglong2*)(d)     = make_ulonglong2(dup2(v0.x), dup2(v0.y));
                *(ulonglong2*)(d + 2) = make_ulonglong2(dup2(v0.z), dup2(v0.w));
                *(ulonglong2*)(d + 4) = make_ulonglong2(dup2(v1.x), dup2(v1.y));
                *(ulonglong2*)(d + 6) = make_ulonglong2(dup2(v1.z), dup2(v1.w));
            }
            nbar(1);
            if (atid == 0) atomicAdd_block(&s_aStage, 1u);

            if (full) {
                const u64* sp = sh0 + (((s & 1)) * Hn + w * 32) * NBAT + bp * 2;
                const u64* wp = wAs + (In + w * 32) * NCOL + cp * 2;
#pragma unroll 8
                for (int i = 0; i < 32; i++) {
                    ulonglong2 sv = *(const ulonglong2*)(sp + i * NBAT);
                    ulonglong2 wv = *(const ulonglong2*)(wp + i * NCOL);
                    fma2(a00, sv.x, wv.x); fma2(a01, sv.x, wv.y);
                    fma2(a10, sv.y, wv.x); fma2(a11, sv.y, wv.y);
                }
                u64* rr = redA + atid * RS;
                *(ulonglong2*)(rr)     = make_ulonglong2(a00, a01);
                *(ulonglong2*)(rr + 2) = make_ulonglong2(a10, a11);
                nbar(1);
                if (atid < 128) {
                    u64 acc = biasA[rc];
#pragma unroll
                    for (int ww = 0; ww < 8; ww++)
                        acc = add2(acc, redA[(ww * 32 + ridx) * RS + raid]);
                    float hn = blend(acc, hprev);
                    hprev = hn;
                    stcgf(&g_h0[((s & 1) * Hn + C) * Bn + B], hn);  // coalesced 32B groups
                }
                nbar(1);
                if (atid == 0) g_arrive(ctrA);
            }
        }
        if (atid < 128) out[OFF + (size_t)B * Hn + C] = hprev;

    } else {
        // ================= B-engine (warps 0-7) =================
        const int btid = tid;
        const int w  = btid >> 5, ln = btid & 31;
        const int bp = ln >> 3,  cp = ln & 7;
        const int rb = btid & 7, rc = btid >> 3;           // batch-minor map
        const int ridx = (rb >> 1) * 8 + (rc >> 1);
        const int raid = (rb & 1) * 2 + (rc & 1);
        const int C = col0 + rc, B = b0g + rb;
        float hprev = 0.0f;

        for (int t = 0; t < Tn; t++) {
            s_poll_w(&s_aStage, t + 2);       // h0[t] staged in sh0[(t+1)&1]
            g_poll_w(ctrB, 16 * t);           // h1[t-1] visible

            {   // stage row btid of h1[t-1]
                const float* src = g_h1 + ((((t + 1) & 1)) * Hn + btid) * Bn + b0g;
                float4 v0 = ldcgf4(src);
                float4 v1 = ldcgf4(src + 4);
                u64* d = sh1 + btid * NBAT;
                *(ulonglong2*)(d)     = make_ulonglong2(dup2(v0.x), dup2(v0.y));
                *(ulonglong2*)(d + 2) = make_ulonglong2(dup2(v0.z), dup2(v0.w));
                *(ulonglong2*)(d + 4) = make_ulonglong2(dup2(v1.x), dup2(v1.y));
                *(ulonglong2*)(d + 6) = make_ulonglong2(dup2(v1.z), dup2(v1.w));
            }
            nbar(2);

            u64 a00 = 0, a01 = 0, a10 = 0, a11 = 0;
            {
                const int p0 = (t + 1) & 1;
                const u64* s0 = sh0 + (p0 * Hn + w * 32) * NBAT + bp * 2;
                const u64* w1 = wBs + (w * 32) * NCOL + cp * 2;
                const u64* s1 = sh1 + (w * 32) * NBAT + bp * 2;
                const u64* w2 = wBs + (Hn + w * 32) * NCOL + cp * 2;
#pragma unroll 8
                for (int i = 0; i < 32; i++) {
                    ulonglong2 sv = *(const ulonglong2*)(s0 + i * NBAT);
                    ulonglong2 wv = *(const ulonglong2*)(w1 + i * NCOL);
                    fma2(a00, sv.x, wv.x); fma2(a01, sv.x, wv.y);
                    fma2(a10, sv.y, wv.x); fma2(a11, sv.y, wv.y);
                    sv = *(const ulonglong2*)(s1 + i * NBAT);
                    wv = *(const ulonglong2*)(w2 + i * NCOL);
                    fma2(a00, sv.x, wv.x); fma2(a01, sv.x, wv.y);
                    fma2(a10, sv.y, wv.x); fma2(a11, sv.y, wv.y);
                }
            }
            {
                u64* rr = redB + btid * RS;
                *(ulonglong2*)(rr)     = make_ulonglong2(a00, a01);
                *(ulonglong2*)(rr + 2) = make_ulonglong2(a10, a11);
            }
            nbar(2);
            if (btid == 0) atomicAdd_block(&s_bDone, 1u);

            if (btid < 128) {
                u64 acc = biasB[rc];
#pragma unroll
                for (int ww = 0; ww < 8; ww++)
                    acc = add2(acc, redB[(ww * 32 + ridx) * RS + raid]);
                float hn = blend(acc, hprev);
                hprev = hn;
                stcgf(&g_h1[((t & 1) * Hn + C) * Bn + B], hn);   // coalesced 32B groups
                out[((size_t)B * Tn + t) * Hn + C] = hn;         // off critical path
            }
            nbar(2);
            if (btid == 0) g_arrive(ctrB);
        }
        if (btid < 128) out[OFF + (size_t)Bn * Hn + (size_t)B * Hn + C] = hprev;
    }
}

// ---------------- launch ----------------
extern "C" void kernel_launch(void* const* d_in, const int* in_sizes, int n_in,
                              void* d_out, int out_size) {
    const float* x    = (const float*)d_in[0];
    const float* Wih0 = (const float*)d_in[1];
    const float* Whh0 = (const float*)d_in[2];
    const float* bh0  = (const float*)d_in[3];
    const float* Wax0 = (const float*)d_in[4];
    const float* Wah0 = (const float*)d_in[5];
    const float* ba0  = (const float*)d_in[6];
    const float* Wih1 = (const float*)d_in[7];
    const float* Whh1 = (const float*)d_in[8];
    const float* bh1  = (const float*)d_in[9];
    const float* Wax1 = (const float*)d_in[10];
    const float* Wah1 = (const float*)d_in[11];
    const float* ba1  = (const float*)d_in[12];
    float* out = (float*)d_out;

    const int smem = (KA * NCOL + KB * NCOL
                    + 2 * Hn * NBAT + Hn * NBAT
                    + 2 * 256 * RS
                    + 2 * NCOL) * 8;
    cudaFuncSetAttribute(rnn_kernel, cudaFuncAttributeMaxDynamicSharedMemorySize, smem);

    prep_kernel<<<Tn, PT>>>(x);
    rnn_kernel<<<GCTA, THREADS, smem>>>(
        Wih0, Whh0, bh0, Wax0, Wah0, ba0,
        Wih1, Whh1, bh1, Wax1, Wah1, ba1,
        out);
}

// round 13
// speedup vs baseline: 2.4328x; 1.0331x over previous
#include <cuda_runtime.h>
#include <cstdint>

#define Bn 64
#define Tn 2048
#define In 128
#define Hn 256
#define THREADS 512
#define PT 256
#define NCOL 16
#define NBAT 8
#define NCG  16
#define NBG  8
#define GCTA 128
#define KA 384
#define KB 512
#define RP 18                   // red row stride (u64), bank-skewed

typedef unsigned long long u64;

// ---------------- device scratch ----------------
__device__ __align__(256) u64   g_xT2[(size_t)Tn * In * Bn];  // x dup'd {v,v}: [t][k][b]
__device__ __align__(256) float g_h0[2 * Hn * Bn];            // [buf][k][b]
__device__ __align__(256) float g_h1[2 * Hn * Bn];
__device__ __align__(128) unsigned g_ctrA[NBG * 32];
__device__ __align__(128) unsigned g_ctrB[NBG * 32];

// ---------------- packed f32x2 helpers ----------------
__device__ __forceinline__ void fma2(u64 &d, u64 a, u64 b) {
    asm("fma.rn.f32x2 %0, %1, %2, %0;" : "+l"(d) : "l"(a), "l"(b));
}
__device__ __forceinline__ u64 add2(u64 a, u64 b) {
    u64 d; asm("add.rn.f32x2 %0, %1, %2;" : "=l"(d) : "l"(a), "l"(b)); return d;
}
__device__ __forceinline__ u64 dup2(float f) {
    u64 d; asm("mov.b64 %0, {%1, %1};" : "=l"(d) : "f"(f)); return d;
}
__device__ __forceinline__ u64 pack2(float lo, float hi) {
    u64 d; asm("mov.b64 %0, {%1, %2};" : "=l"(d) : "f"(lo), "f"(hi)); return d;
}
__device__ __forceinline__ float lo2(u64 v) { return __uint_as_float((unsigned)(v & 0xffffffffull)); }
__device__ __forceinline__ float hi2(u64 v) { return __uint_as_float((unsigned)(v >> 32)); }

__device__ __forceinline__ float4 ldcgf4(const float* p) {
    float4 v;
    asm volatile("ld.global.cg.v4.f32 {%0, %1, %2, %3}, [%4];"
                 : "=f"(v.x), "=f"(v.y), "=f"(v.z), "=f"(v.w) : "l"(p));
    return v;
}
__device__ __forceinline__ void stcgf(float* p, float v) {
    asm volatile("st.global.cg.f32 [%0], %1;" :: "l"(p), "f"(v) : "memory");
}
__device__ __forceinline__ void g_arrive(unsigned* c) {
    unsigned old;
    asm volatile("atom.release.gpu.global.add.u32 %0, [%1], 1;" : "=r"(old) : "l"(c) : "memory");
}
__device__ __forceinline__ void g_poll(unsigned* c, int tgt) {
    if (tgt <= 0) return;
    int v;
    do { asm volatile("ld.acquire.gpu.global.u32 %0, [%1];" : "=r"(v) : "l"(c) : "memory"); } while (v < tgt);
}
__device__ __forceinline__ void s_poll(volatile unsigned* c, int tgt) {
    if (tgt <= 0) return;
    while ((int)(*c) < tgt) { }
    __threadfence_block();
}
__device__ __forceinline__ void nbar(int id) {
    asm volatile("bar.sync %0, 256;" :: "r"(id) : "memory");
}

// fused blend: h' = sg(a)*tanh(c) + (1-sg(a))*hp
__device__ __forceinline__ float blend(u64 acc, float hp) {
    float cnd = fmaxf(lo2(acc), -15.0f);
    float alp = fmaxf(hi2(acc), -30.0f);
    float v = __expf(-2.0f * cnd);
    float u = __expf(-alp);
    float t2 = 1.0f + v;
    float num = __fmaf_rn(u * hp, t2, 1.0f - v);
    float den = (1.0f + u) * t2;
    return __fdividef(num, den);
}

// 4x4 FFMA2 tile: batches from S01/S23 (dup'd), cols from W01/W23 ({wc,wa})
#define FMA16(S01, S23, W01, W23)                                   \
    fma2(a00, S01.x, W01.x); fma2(a01, S01.x, W01.y);               \
    fma2(a02, S01.x, W23.x); fma2(a03, S01.x, W23.y);               \
    fma2(a10, S01.y, W01.x); fma2(a11, S01.y, W01.y);               \
    fma2(a12, S01.y, W23.x); fma2(a13, S01.y, W23.y);               \
    fma2(a20, S23.x, W01.x); fma2(a21, S23.x, W01.y);               \
    fma2(a22, S23.x, W23.x); fma2(a23, S23.x, W23.y);               \
    fma2(a30, S23.y, W01.x); fma2(a31, S23.y, W01.y);               \
    fma2(a32, S23.y, W23.x); fma2(a33, S23.y, W23.y);

#define SHRED(a)                                                    \
    a = add2(a, __shfl_xor_sync(0xffffffffu, a, 8));                \
    a = add2(a, __shfl_xor_sync(0xffffffffu, a, 16));

#define ZERO16() a00=a01=a02=a03=a10=a11=a12=a13=a20=a21=a22=a23=a30=a31=a32=a33=0ull

// ---------------- prep ----------------
__global__ void prep_kernel(const float* __restrict__ x) {
    __shared__ float s[In][65];
    const int t = blockIdx.x;
    const int tid = threadIdx.x;
    for (int idx = tid; idx < Bn * In; idx += PT) {
        int b = idx >> 7, i = idx & (In - 1);
        s[i][b] = x[((size_t)b * Tn + t) * In + i];
    }
    __syncthreads();
    for (int idx = tid; idx < In * Bn; idx += PT) {
        int i = idx >> 6, b = idx & (Bn - 1);
        g_xT2[((size_t)t * In + i) * Bn + b] = dup2(s[i][b]);
    }
    if (t == 0 && tid < NBG) { g_ctrA[tid * 32] = 0u; g_ctrB[tid * 32] = 0u; }
    if (t < 2) {
        for (int i = tid; i < Hn * Bn; i += PT) {
            g_h0[t * Hn * Bn + i] = 0.0f;
            g_h1[t * Hn * Bn + i] = 0.0f;
        }
    }
}

// ---------------- persistent pipelined RNN kernel ----------------
__global__ void __launch_bounds__(THREADS, 1) rnn_kernel(
    const float* __restrict__ Wih0, const float* __restrict__ Whh0,
    const float* __restrict__ bh0,  const float* __restrict__ Wax0,
    const float* __restrict__ Wah0, const float* __restrict__ ba0,
    const float* __restrict__ Wih1, const float* __restrict__ Whh1,
    const float* __restrict__ bh1,  const float* __restrict__ Wax1,
    const float* __restrict__ Wah1, const float* __restrict__ ba1,
    float* __restrict__ out)
{
    extern __shared__ u64 sm[];
    u64* wAs   = sm;                        // [KA][16] {wc,wa}
    u64* wBs   = wAs + KA * NCOL;           // [KB][16]
    u64* sh0   = wBs + KB * NCOL;           // [2][Hn][8] dup'd
    u64* sh1   = sh0 + 2 * Hn * NBAT;       // [Hn][8] dup'd
    u64* redA  = sh1 + Hn * NBAT;           // [64][RP]
    u64* redB  = redA + 64 * RP;            // [64][RP]
    u64* biasA = redB + 64 * RP;            // [16]
    u64* biasB = biasA + NCOL;              // [16]
    __shared__ unsigned s_aStage, s_bDone;

    const int tid  = threadIdx.x;
    const int cg   = blockIdx.x & (NCG - 1);
    const int bg   = blockIdx.x >> 4;
    const int col0 = cg * NCOL;
    const int b0g  = bg * NBAT;
    unsigned* ctrA = &g_ctrA[bg * 32];
    unsigned* ctrB = &g_ctrB[bg * 32];

    for (int idx = tid; idx < KA * NCOL; idx += THREADS) {
        int k = idx >> 4, c = idx & 15, C = col0 + c;
        float wc = (k < In) ? Wih0[k * Hn + C] : Whh0[(k - In) * Hn + C];
        float wa = (k < In) ? Wax0[k * Hn + C] : Wah0[(k - In) * Hn + C];
        wAs[idx] = pack2(wc, wa);
    }
    for (int idx = tid; idx < KB * NCOL; idx += THREADS) {
        int k = idx >> 4, c = idx & 15, C = col0 + c;
        float wc = (k < Hn) ? Wih1[k * Hn + C] : Whh1[(k - Hn) * Hn + C];
        float wa = (k < Hn) ? Wax1[k * Hn + C] : Wah1[(k - Hn) * Hn + C];
        wBs[idx] = pack2(wc, wa);
    }
    if (tid < NCOL) {
        biasA[tid] = pack2(bh0[col0 + tid], ba0[col0 + tid]);
        biasB[tid] = pack2(bh1[col0 + tid], ba1[col0 + tid]);
    }
    if (tid == 0) { s_aStage = 0u; s_bDone = 0u; }
    __syncthreads();

    const size_t OFF = (size_t)Bn * Tn * Hn;

    if (tid >= 256) {
        // ================= A-engine (warps 8-15) =================
        const int atid  = tid - 256;
        const int ln    = atid & 31;
        const int tl    = ln & 7;             // tile: btile | ctile<<1
        const int btile = tl & 1;
        const int ctile = tl >> 1;
        const int ks    = atid >> 3;          // 0..31 K-slice
        // epilogue cell
        const int rb = atid >> 4, rc = atid & 15;              // atid<128
        const int etl  = (rb >> 2) | ((rc >> 2) << 1);
        const int eidx = (rb & 3) * 4 + (rc & 3);
        const int C = col0 + rc, B = b0g + rb;
        float hprev = 0.0f;

        u64 a00,a01,a02,a03,a10,a11,a12,a13,a20,a21,a22,a23,a30,a31,a32,a33;

        // x-part of step s into acc (K_x = 4 per thread)
        auto xpart = [&](int s) {
            const u64* xp = g_xT2 + ((size_t)s * In + ks * 4) * Bn + b0g + btile * 4;
            const u64* wp = wAs + (ks * 4) * NCOL + ctile * 4;
#pragma unroll
            for (int i = 0; i < 4; i++) {
                ulonglong2 S01 = *(const ulonglong2*)(xp + (size_t)i * Bn);
                ulonglong2 S23 = *(const ulonglong2*)(xp + (size_t)i * Bn + 2);
                ulonglong2 W01 = *(const ulonglong2*)(wp + i * NCOL);
                ulonglong2 W23 = *(const ulonglong2*)(wp + i * NCOL + 2);
                FMA16(S01, S23, W01, W23)
            }
        };

        ZERO16();
        xpart(0);

        for (int s = 0; s <= Tn; s++) {
            const bool full = (s < Tn);
            s_poll(&s_bDone, s - 2);          // sh0[s&1] free
            g_poll(ctrA, 16 * s);             // h0[s-1] visible

            {   // stage row atid of h0[s-1] (dup'd)
                const float* src = g_h0 + ((((s + 1) & 1)) * Hn + atid) * Bn + b0g;
                float4 v0 = ldcgf4(src);
                float4 v1 = ldcgf4(src + 4);
                u64* d = sh0 + (((s & 1)) * Hn + atid) * NBAT;
                *(ulonglong2*)(d)     = make_ulonglong2(dup2(v0.x), dup2(v0.y));
                *(ulonglong2*)(d + 2) = make_ulonglong2(dup2(v0.z), dup2(v0.w));
                *(ulonglong2*)(d + 4) = make_ulonglong2(dup2(v1.x), dup2(v1.y));
                *(ulonglong2*)(d + 6) = make_ulonglong2(dup2(v1.z), dup2(v1.w));
            }
            nbar(1);
            if (atid == 0) atomicAdd_block(&s_aStage, 1u);

            if (full) {
                // h-part: 8 k from sh0[s&1]
                const u64* sp = sh0 + (((s & 1)) * Hn + ks * 8) * NBAT + btile * 4;
                const u64* wp = wAs + (In + ks * 8) * NCOL + ctile * 4;
#pragma unroll
                for (int i = 0; i < 8; i++) {
                    ulonglong2 S01 = *(const ulonglong2*)(sp + i * NBAT);
                    ulonglong2 S23 = *(const ulonglong2*)(sp + i * NBAT + 2);
                    ulonglong2 W01 = *(const ulonglong2*)(wp + i * NCOL);
                    ulonglong2 W23 = *(const ulonglong2*)(wp + i * NCOL + 2);
                    FMA16(S01, S23, W01, W23)
                }
                // cross-K shuffle reduce (xor 8, 16): lanes with same tile
                SHRED(a00) SHRED(a01) SHRED(a02) SHRED(a03)
                SHRED(a10) SHRED(a11) SHRED(a12) SHRED(a13)
                SHRED(a20) SHRED(a21) SHRED(a22) SHRED(a23)
                SHRED(a30) SHRED(a31) SHRED(a32) SHRED(a33)
                if (ln < 8) {
                    u64* rr = redA + ((atid >> 5) * 8 + tl) * RP;
                    *(ulonglong2*)(rr +  0) = make_ulonglong2(a00, a01);
                    *(ulonglong2*)(rr +  2) = make_ulonglong2(a02, a03);
                    *(ulonglong2*)(rr +  4) = make_ulonglong2(a10, a11);
                    *(ulonglong2*)(rr +  6) = make_ulonglong2(a12, a13);
                    *(ulonglong2*)(rr +  8) = make_ulonglong2(a20, a21);
                    *(ulonglong2*)(rr + 10) = make_ulonglong2(a22, a23);
                    *(ulonglong2*)(rr + 12) = make_ulonglong2(a30, a31);
                    *(ulonglong2*)(rr + 14) = make_ulonglong2(a32, a33);
                }
            }

            // x prefetch for s+1 (fills shadow; resets acc)
            ZERO16();
            if (s + 1 < Tn) xpart(s + 1);

            if (full) {
                nbar(1);
                if (atid < 128) {
                    u64 acc = biasA[rc];
#pragma unroll
                    for (int w2 = 0; w2 < 8; w2++)
                        acc = add2(acc, redA[(w2 * 8 + etl) * RP + eidx]);
                    float hn = blend(acc, hprev);
                    hprev = hn;
                    stcgf(&g_h0[((s & 1) * Hn + C) * Bn + B], hn);
                }
                nbar(1);
                if (atid == 0) g_arrive(ctrA);
            }
        }
        if (atid < 128) out[OFF + (size_t)B * Hn + C] = hprev;

    } else {
        // ================= B-engine (warps 0-7) =================
        const int btid  = tid;
        const int ln    = btid & 31;
        const int tl    = ln & 7;
        const int btile = tl & 1;
        const int ctile = tl >> 1;
        const int ks    = btid >> 3;          // 0..31
        const int rb = btid >> 4, rc = btid & 15;
        const int etl  = (rb >> 2) | ((rc >> 2) << 1);
        const int eidx = (rb & 3) * 4 + (rc & 3);
        const int C = col0 + rc, B = b0g + rb;
        float hprev = 0.0f;

        u64 a00,a01,a02,a03,a10,a11,a12,a13,a20,a21,a22,a23,a30,a31,a32,a33;

        for (int t = 0; t < Tn; t++) {
            s_poll(&s_aStage, t + 2);         // h0[t] staged in sh0[(t+1)&1]
            g_poll(ctrB, 16 * t);             // h1[t-1] visible

            {   // stage row btid of h1[t-1]
                const float* src = g_h1 + ((((t + 1) & 1)) * Hn + btid) * Bn + b0g;
                float4 v0 = ldcgf4(src);
                float4 v1 = ldcgf4(src + 4);
                u64* d = sh1 + btid * NBAT;
                *(ulonglong2*)(d)     = make_ulonglong2(dup2(v0.x), dup2(v0.y));
                *(ulonglong2*)(d + 2) = make_ulonglong2(dup2(v0.z), dup2(v0.w));
                *(ulonglong2*)(d + 4) = make_ulonglong2(dup2(v1.x), dup2(v1.y));
                *(ulonglong2*)(d + 6) = make_ulonglong2(dup2(v1.z), dup2(v1.w));
            }
            nbar(2);

            ZERO16();
            {   // h0[t] x wB1 : 8 k
                const int p0 = (t + 1) & 1;
                const u64* sp = sh0 + (p0 * Hn + ks * 8) * NBAT + btile * 4;
                const u64* wp = wBs + (ks * 8) * NCOL + ctile * 4;
#pragma unroll
                for (int i = 0; i < 8; i++) {
                    ulonglong2 S01 = *(const ulonglong2*)(sp + i * NBAT);
                    ulonglong2 S23 = *(const ulonglong2*)(sp + i * NBAT + 2);
                    ulonglong2 W01 = *(const ulonglong2*)(wp + i * NCOL);
                    ulonglong2 W23 = *(const ulonglong2*)(wp + i * NCOL + 2);
                    FMA16(S01, S23, W01, W23)
                }
            }
            {   // h1[t-1] x wB2 : 8 k
                const u64* sp = sh1 + (ks * 8) * NBAT + btile * 4;
                const u64* wp = wBs + (Hn + ks * 8) * NCOL + ctile * 4;
#pragma unroll
                for (int i = 0; i < 8; i++) {
                    ulonglong2 S01 = *(const ulonglong2*)(sp + i * NBAT);
                    ulonglong2 S23 = *(const ulonglong2*)(sp + i * NBAT + 2);
                    ulonglong2 W01 = *(const ulonglong2*)(wp + i * NCOL);
                    ulonglong2 W23 = *(const ulonglong2*)(wp + i * NCOL + 2);
                    FMA16(S01, S23, W01, W23)
                }
            }
            SHRED(a00) SHRED(a01) SHRED(a02) SHRED(a03)
            SHRED(a10) SHRED(a11) SHRED(a12) SHRED(a13)
            SHRED(a20) SHRED(a21) SHRED(a22) SHRED(a23)
            SHRED(a30) SHRED(a31) SHRED(a32) SHRED(a33)
            if (ln < 8) {
                u64* rr = redB + ((btid >> 5) * 8 + tl) * RP;
                *(ulonglong2*)(rr +  0) = make_ulonglong2(a00, a01);
                *(ulonglong2*)(rr +  2) = make_ulonglong2(a02, a03);
                *(ulonglong2*)(rr +  4) = make_ulonglong2(a10, a11);
                *(ulonglong2*)(rr +  6) = make_ulonglong2(a12, a13);
                *(ulonglong2*)(rr +  8) = make_ulonglong2(a20, a21);
                *(ulonglong2*)(rr + 10) = make_ulonglong2(a22, a23);
                *(ulonglong2*)(rr + 12) = make_ulonglong2(a30, a31);
                *(ulonglong2*)(rr + 14) = make_ulonglong2(a32, a33);
            }
            nbar(2);
            if (btid == 0) atomicAdd_block(&s_bDone, 1u);    // sh0 reads done

            if (btid < 128) {
                u64 acc = biasB[rc];
#pragma unroll
                for (int w2 = 0; w2 < 8; w2++)
                    acc = add2(acc, redB[(w2 * 8 + etl) * RP + eidx]);
                float hn = blend(acc, hprev);
                hprev = hn;
                stcgf(&g_h1[((t & 1) * Hn + C) * Bn + B], hn);
                out[((size_t)B * Tn + t) * Hn + C] = hn;
            }
            nbar(2);
            if (btid == 0) g_arrive(ctrB);
        }
        if (btid < 128) out[OFF + (size_t)Bn * Hn + (size_t)B * Hn + C] = hprev;
    }
}

// ---------------- launch ----------------
extern "C" void kernel_launch(void* const* d_in, const int* in_sizes, int n_in,
                              void* d_out, int out_size) {
    const float* x    = (const float*)d_in[0];
    const float* Wih0 = (const float*)d_in[1];
    const float* Whh0 = (const float*)d_in[2];
    const float* bh0  = (const float*)d_in[3];
    const float* Wax0 = (const float*)d_in[4];
    const float* Wah0 = (const float*)d_in[5];
    const float* ba0  = (const float*)d_in[6];
    const float* Wih1 = (const float*)d_in[7];
    const float* Whh1 = (const float*)d_in[8];
    const float* bh1  = (const float*)d_in[9];
    const float* Wax1 = (const float*)d_in[10];
    const float* Wah1 = (const float*)d_in[11];
    const float* ba1  = (const float*)d_in[12];
    float* out = (float*)d_out;

    const int smem = (KA * NCOL + KB * NCOL
                    + 2 * Hn * NBAT + Hn * NBAT
                    + 2 * 64 * RP
                    + 2 * NCOL) * 8;
    cudaFuncSetAttribute(rnn_kernel, cudaFuncAttributeMaxDynamicSharedMemorySize, smem);

    prep_kernel<<<Tn, PT>>>(x);
    rnn_kernel<<<GCTA, THREADS, smem>>>(
        Wih0, Whh0, bh0, Wax0, Wah0, ba0,
        Wih1, Whh1, bh1, Wax1, Wah1, ba1,
        out);
}

// round 14
// speedup vs baseline: 2.6047x; 1.0706x over previous
#include <cuda_runtime.h>
#include <cstdint>

#define Bn 64
#define Tn 2048
#define In 128
#define Hn 256
#define THREADS 512
#define PT 256
#define NCOL 16
#define NBAT 8
#define NCG  16
#define NBG  8
#define GCTA 128
#define KA 384
#define KB 512
#define RP 18

typedef unsigned long long u64;

__device__ __align__(256) u64   g_xT2[(size_t)Tn * In * Bn];
__device__ __align__(256) float g_h0[2 * Hn * Bn];
__device__ __align__(256) float g_h1[2 * Hn * Bn];
__device__ __align__(128) unsigned g_ctrA[NBG * 32];
__device__ __align__(128) unsigned g_ctrB[NBG * 32];

__device__ __forceinline__ void fma2(u64 &d, u64 a, u64 b) {
    asm("fma.rn.f32x2 %0, %1, %2, %0;" : "+l"(d) : "l"(a), "l"(b));
}
__device__ __forceinline__ u64 add2(u64 a, u64 b) {
    u64 d; asm("add.rn.f32x2 %0, %1, %2;" : "=l"(d) : "l"(a), "l"(b)); return d;
}
__device__ __forceinline__ u64 dup2(float f) {
    u64 d; asm("mov.b64 %0, {%1, %1};" : "=l"(d) : "f"(f)); return d;
}
__device__ __forceinline__ u64 pack2(float lo, float hi) {
    u64 d; asm("mov.b64 %0, {%1, %2};" : "=l"(d) : "f"(lo), "f"(hi)); return d;
}
__device__ __forceinline__ float lo2(u64 v) { return __uint_as_float((unsigned)(v & 0xffffffffull)); }
__device__ __forceinline__ float hi2(u64 v) { return __uint_as_float((unsigned)(v >> 32)); }

__device__ __forceinline__ void ldcg2(const u64* p, u64 &a, u64 &b) {
    asm volatile("ld.global.cg.v2.u64 {%0, %1}, [%2];" : "=l"(a), "=l"(b) : "l"(p));
}
__device__ __forceinline__ float4 ldcgf4(const float* p) {
    float4 v;
    asm volatile("ld.global.cg.v4.f32 {%0, %1, %2, %3}, [%4];"
                 : "=f"(v.x), "=f"(v.y), "=f"(v.z), "=f"(v.w) : "l"(p));
    return v;
}
__device__ __forceinline__ void stcgf(float* p, float v) {
    asm volatile("st.global.cg.f32 [%0], %1;" :: "l"(p), "f"(v) : "memory");
}
__device__ __forceinline__ void g_arrive(unsigned* c) {
    unsigned old;
    asm volatile("atom.release.gpu.global.add.u32 %0, [%1], 1;" : "=r"(old) : "l"(c) : "memory");
}
__device__ __forceinline__ void g_poll(unsigned* c, int tgt) {
    if (tgt <= 0) return;
    int v;
    do { asm volatile("ld.acquire.gpu.global.u32 %0, [%1];" : "=r"(v) : "l"(c) : "memory"); } while (v < tgt);
}
__device__ __forceinline__ void s_poll(volatile unsigned* c, int tgt) {
    if (tgt <= 0) return;
    while ((int)(*c) < tgt) { }
    __threadfence_block();
}
__device__ __forceinline__ void nbar(int id) {
    asm volatile("bar.sync %0, 256;" :: "r"(id) : "memory");
}

__device__ __forceinline__ float blend(u64 acc, float hp) {
    float cnd = fmaxf(lo2(acc), -15.0f);
    float alp = fmaxf(hi2(acc), -30.0f);
    float v = __expf(-2.0f * cnd);
    float u = __expf(-alp);
    float t2 = 1.0f + v;
    float num = __fmaf_rn(u * hp, t2, 1.0f - v);
    float den = (1.0f + u) * t2;
    return __fdividef(num, den);
}

#define FMA16(S01, S23, W01, W23)                                   \
    fma2(a00, S01.x, W01.x); fma2(a01, S01.x, W01.y);               \
    fma2(a02, S01.x, W23.x); fma2(a03, S01.x, W23.y);               \
    fma2(a10, S01.y, W01.x); fma2(a11, S01.y, W01.y);               \
    fma2(a12, S01.y, W23.x); fma2(a13, S01.y, W23.y);               \
    fma2(a20, S23.x, W01.x); fma2(a21, S23.x, W01.y);               \
    fma2(a22, S23.x, W23.x); fma2(a23, S23.x, W23.y);               \
    fma2(a30, S23.y, W01.x); fma2(a31, S23.y, W01.y);               \
    fma2(a32, S23.y, W23.x); fma2(a33, S23.y, W23.y);

#define SHRED(a)                                                    \
    a = add2(a, __shfl_xor_sync(0xffffffffu, a, 8));                \
    a = add2(a, __shfl_xor_sync(0xffffffffu, a, 16));

#define ZERO16() a00=a01=a02=a03=a10=a11=a12=a13=a20=a21=a22=a23=a30=a31=a32=a33=0ull

__global__ void prep_kernel(const float* __restrict__ x) {
    __shared__ float s[In][65];
    const int t = blockIdx.x;
    const int tid = threadIdx.x;
    for (int idx = tid; idx < Bn * In; idx += PT) {
        int b = idx >> 7, i = idx & (In - 1);
        s[i][b] = x[((size_t)b * Tn + t) * In + i];
    }
    __syncthreads();
    for (int idx = tid; idx < In * Bn; idx += PT) {
        int i = idx >> 6, b = idx & (Bn - 1);
        g_xT2[((size_t)t * In + i) * Bn + b] = dup2(s[i][b]);
    }
    if (t == 0 && tid < NBG) { g_ctrA[tid * 32] = 0u; g_ctrB[tid * 32] = 0u; }
    if (t < 2) {
        for (int i = tid; i < Hn * Bn; i += PT) {
            g_h0[t * Hn * Bn + i] = 0.0f;
            g_h1[t * Hn * Bn + i] = 0.0f;
        }
    }
}

__global__ void __launch_bounds__(THREADS, 1) rnn_kernel(
    const float* __restrict__ Wih0, const float* __restrict__ Whh0,
    const float* __restrict__ bh0,  const float* __restrict__ Wax0,
    const float* __restrict__ Wah0, const float* __restrict__ ba0,
    const float* __restrict__ Wih1, const float* __restrict__ Whh1,
    const float* __restrict__ bh1,  const float* __restrict__ Wax1,
    const float* __restrict__ Wah1, const float* __restrict__ ba1,
    float* __restrict__ out)
{
    extern __shared__ u64 sm[];
    u64* wAs   = sm;                        // [KA][16] {wc,wa}
    u64* wBs   = wAs + KA * NCOL;           // [KB][16]
    u64* sh0   = wBs + KB * NCOL;           // [2][Hn][8] dup'd
    u64* sh1   = sh0 + 2 * Hn * NBAT;       // [Hn][8] dup'd
    u64* redA  = sh1 + Hn * NBAT;           // [64][RP]
    u64* redB  = redA + 64 * RP;            // [64][RP]
    u64* biasA = redB + 64 * RP;            // [16]
    u64* biasB = biasA + NCOL;              // [16]
    __shared__ unsigned s_aStage, s_bDone;

    const int tid  = threadIdx.x;
    const int cg   = blockIdx.x & (NCG - 1);
    const int bg   = blockIdx.x >> 4;
    const int col0 = cg * NCOL;
    const int b0g  = bg * NBAT;
    unsigned* ctrA = &g_ctrA[bg * 32];
    unsigned* ctrB = &g_ctrB[bg * 32];

    for (int idx = tid; idx < KA * NCOL; idx += THREADS) {
        int k = idx >> 4, c = idx & 15, C = col0 + c;
        float wc = (k < In) ? Wih0[k * Hn + C] : Whh0[(k - In) * Hn + C];
        float wa = (k < In) ? Wax0[k * Hn + C] : Wah0[(k - In) * Hn + C];
        wAs[idx] = pack2(wc, wa);
    }
    for (int idx = tid; idx < KB * NCOL; idx += THREADS) {
        int k = idx >> 4, c = idx & 15, C = col0 + c;
        float wc = (k < Hn) ? Wih1[k * Hn + C] : Whh1[(k - Hn) * Hn + C];
        float wa = (k < Hn) ? Wax1[k * Hn + C] : Wah1[(k - Hn) * Hn + C];
        wBs[idx] = pack2(wc, wa);
    }
    if (tid < NCOL) {
        biasA[tid] = pack2(bh0[col0 + tid], ba0[col0 + tid]);
        biasB[tid] = pack2(bh1[col0 + tid], ba1[col0 + tid]);
    }
    if (tid == 0) { s_aStage = 0u; s_bDone = 0u; }
    __syncthreads();

    const size_t OFF = (size_t)Bn * Tn * Hn;

    if (tid >= 256) {
        // ================= A-engine (warps 8-15) =================
        const int atid  = tid - 256;
        const int ln    = atid & 31;
        const int tl    = ln & 7;
        const int btile = tl & 1;
        const int ctile = tl >> 1;
        const int ks    = atid >> 3;
        const int rb = atid >> 4, rc = atid & 15;
        const int etl  = (rb >> 2) | ((rc >> 2) << 1);
        const int eidx = (rb & 3) * 4 + (rc & 3);
        const int C = col0 + rc, B = b0g + rb;
        float hprev = 0.0f;

        u64 a00,a01,a02,a03,a10,a11,a12,a13,a20,a21,a22,a23,a30,a31,a32,a33;
        // prefetched x state for the NEXT consumed step (4 k-iters x 32B)
        ulonglong2 xs0[4], xs1[4];

        // issue x-state loads for step s (registers; no FMA — loads fly during the step)
        auto xload = [&](int s) {
            const u64* xp = g_xT2 + ((size_t)s * In + ks * 4) * Bn + b0g + btile * 4;
#pragma unroll
            for (int i = 0; i < 4; i++) {
                ldcg2(xp + (size_t)i * Bn, xs0[i].x, xs0[i].y);
                ldcg2(xp + (size_t)i * Bn + 2, xs1[i].x, xs1[i].y);
            }
        };
        // consume prefetched x regs into acc (weights via LDS)
        auto xfma = [&]() {
            const u64* wp = wAs + (ks * 4) * NCOL + ctile * 4;
#pragma unroll
            for (int i = 0; i < 4; i++) {
                ulonglong2 W01 = *(const ulonglong2*)(wp + i * NCOL);
                ulonglong2 W23 = *(const ulonglong2*)(wp + i * NCOL + 2);
                FMA16(xs0[i], xs1[i], W01, W23)
            }
        };

        xload(0);

        for (int s = 0; s <= Tn; s++) {
            const bool full = (s < Tn);

            ZERO16();
            if (full) xfma();             // x(s) — regs landed during previous step
            if (s + 1 < Tn) xload(s + 1); // issue next loads immediately (fly in background)

            s_poll(&s_bDone, s - 2);      // sh0[s&1] free
            g_poll(ctrA, 16 * s);         // h0[s-1] visible

            {   // stage row atid of h0[s-1] (dup'd)
                const float* src = g_h0 + ((((s + 1) & 1)) * Hn + atid) * Bn + b0g;
                float4 v0 = ldcgf4(src);
                float4 v1 = ldcgf4(src + 4);
                u64* d = sh0 + (((s & 1)) * Hn + atid) * NBAT;
                *(ulonglong2*)(d)     = make_ulonglong2(dup2(v0.x), dup2(v0.y));
                *(ulonglong2*)(d + 2) = make_ulonglong2(dup2(v0.z), dup2(v0.w));
                *(ulonglong2*)(d + 4) = make_ulonglong2(dup2(v1.x), dup2(v1.y));
                *(ulonglong2*)(d + 6) = make_ulonglong2(dup2(v1.z), dup2(v1.w));
            }
            nbar(1);
            if (atid == 0) atomicAdd_block(&s_aStage, 1u);

            if (full) {
                const u64* sp = sh0 + (((s & 1)) * Hn + ks * 8) * NBAT + btile * 4;
                const u64* wp = wAs + (In + ks * 8) * NCOL + ctile * 4;
#pragma unroll
                for (int i = 0; i < 8; i++) {
                    ulonglong2 S01 = *(const ulonglong2*)(sp + i * NBAT);
                    ulonglong2 S23 = *(const ulonglong2*)(sp + i * NBAT + 2);
                    ulonglong2 W01 = *(const ulonglong2*)(wp + i * NCOL);
                    ulonglong2 W23 = *(const ulonglong2*)(wp + i * NCOL + 2);
                    FMA16(S01, S23, W01, W23)
                }
                SHRED(a00) SHRED(a01) SHRED(a02) SHRED(a03)
                SHRED(a10) SHRED(a11) SHRED(a12) SHRED(a13)
                SHRED(a20) SHRED(a21) SHRED(a22) SHRED(a23)
                SHRED(a30) SHRED(a31) SHRED(a32) SHRED(a33)
                if (ln < 8) {
                    u64* rr = redA + ((atid >> 5) * 8 + tl) * RP;
                    *(ulonglong2*)(rr +  0) = make_ulonglong2(a00, a01);
                    *(ulonglong2*)(rr +  2) = make_ulonglong2(a02, a03);
                    *(ulonglong2*)(rr +  4) = make_ulonglong2(a10, a11);
                    *(ulonglong2*)(rr +  6) = make_ulonglong2(a12, a13);
                    *(ulonglong2*)(rr +  8) = make_ulonglong2(a20, a21);
                    *(ulonglong2*)(rr + 10) = make_ulonglong2(a22, a23);
                    *(ulonglong2*)(rr + 12) = make_ulonglong2(a30, a31);
                    *(ulonglong2*)(rr + 14) = make_ulonglong2(a32, a33);
                }
                nbar(1);
                if (atid < 128) {
                    u64 acc = biasA[rc];
#pragma unroll
                    for (int w2 = 0; w2 < 8; w2++)
                        acc = add2(acc, redA[(w2 * 8 + etl) * RP + eidx]);
                    float hn = blend(acc, hprev);
                    hprev = hn;
                    stcgf(&g_h0[((s & 1) * Hn + C) * Bn + B], hn);
                }
                nbar(1);
                if (atid == 0) g_arrive(ctrA);
            }
        }
        if (atid < 128) out[OFF + (size_t)B * Hn + C] = hprev;

    } else {
        // ================= B-engine (warps 0-7) =================
        const int btid  = tid;
        const int ln    = btid & 31;
        const int tl    = ln & 7;
        const int btile = tl & 1;
        const int ctile = tl >> 1;
        const int ks    = btid >> 3;
        const int rb = btid >> 4, rc = btid & 15;
        const int etl  = (rb >> 2) | ((rc >> 2) << 1);
        const int eidx = (rb & 3) * 4 + (rc & 3);
        const int C = col0 + rc, B = b0g + rb;
        float hprev = 0.0f;

        u64 a00,a01,a02,a03,a10,a11,a12,a13,a20,a21,a22,a23,a30,a31,a32,a33;

        for (int t = 0; t < Tn; t++) {
            s_poll(&s_aStage, t + 2);
            g_poll(ctrB, 16 * t);

            {   // stage row btid of h1[t-1]
                const float* src = g_h1 + ((((t + 1) & 1)) * Hn + btid) * Bn + b0g;
                float4 v0 = ldcgf4(src);
                float4 v1 = ldcgf4(src + 4);
                u64* d = sh1 + btid * NBAT;
                *(ulonglong2*)(d)     = make_ulonglong2(dup2(v0.x), dup2(v0.y));
                *(ulonglong2*)(d + 2) = make_ulonglong2(dup2(v0.z), dup2(v0.w));
                *(ulonglong2*)(d + 4) = make_ulonglong2(dup2(v1.x), dup2(v1.y));
                *(ulonglong2*)(d + 6) = make_ulonglong2(dup2(v1.z), dup2(v1.w));
            }
            nbar(2);

            ZERO16();
            {
                const int p0 = (t + 1) & 1;
                const u64* sp = sh0 + (p0 * Hn + ks * 8) * NBAT + btile * 4;
                const u64* wp = wBs + (ks * 8) * NCOL + ctile * 4;
#pragma unroll
                for (int i = 0; i < 8; i++) {
                    ulonglong2 S01 = *(const ulonglong2*)(sp + i * NBAT);
                    ulonglong2 S23 = *(const ulonglong2*)(sp + i * NBAT + 2);
                    ulonglong2 W01 = *(const ulonglong2*)(wp + i * NCOL);
                    ulonglong2 W23 = *(const ulonglong2*)(wp + i * NCOL + 2);
                    FMA16(S01, S23, W01, W23)
                }
            }
            {
                const u64* sp = sh1 + (ks * 8) * NBAT + btile * 4;
                const u64* wp = wBs + (Hn + ks * 8) * NCOL + ctile * 4;
#pragma unroll
                for (int i = 0; i < 8; i++) {
                    ulonglong2 S01 = *(const ulonglong2*)(sp + i * NBAT);
                    ulonglong2 S23 = *(const ulonglong2*)(sp + i * NBAT + 2);
                    ulonglong2 W01 = *(const ulonglong2*)(wp + i * NCOL);
                    ulonglong2 W23 = *(const ulonglong2*)(wp + i * NCOL + 2);
                    FMA16(S01, S23, W01, W23)
                }
            }
            SHRED(a00) SHRED(a01) SHRED(a02) SHRED(a03)
            SHRED(a10) SHRED(a11) SHRED(a12) SHRED(a13)
            SHRED(a20) SHRED(a21) SHRED(a22) SHRED(a23)
            SHRED(a30) SHRED(a31) SHRED(a32) SHRED(a33)
            if (ln < 8) {
                u64* rr = redB + ((btid >> 5) * 8 + tl) * RP;
                *(ulonglong2*)(rr +  0) = make_ulonglong2(a00, a01);
                *(ulonglong2*)(rr +  2) = make_ulonglong2(a02, a03);
                *(ulonglong2*)(rr +  4) = make_ulonglong2(a10, a11);
                *(ulonglong2*)(rr +  6) = make_ulonglong2(a12, a13);
                *(ulonglong2*)(rr +  8) = make_ulonglong2(a20, a21);
                *(ulonglong2*)(rr + 10) = make_ulonglong2(a22, a23);
                *(ulonglong2*)(rr + 12) = make_ulonglong2(a30, a31);
                *(ulonglong2*)(rr + 14) = make_ulonglong2(a32, a33);
            }
            nbar(2);
            if (btid == 0) atomicAdd_block(&s_bDone, 1u);

            if (btid < 128) {
                u64 acc = biasB[rc];
#pragma unroll
                for (int w2 = 0; w2 < 8; w2++)
                    acc = add2(acc, redB[(w2 * 8 + etl) * RP + eidx]);
                float hn = blend(acc, hprev);
                hprev = hn;
                stcgf(&g_h1[((t & 1) * Hn + C) * Bn + B], hn);
                out[((size_t)B * Tn + t) * Hn + C] = hn;
            }
            nbar(2);
            if (btid == 0) g_arrive(ctrB);
        }
        if (btid < 128) out[OFF + (size_t)Bn * Hn + (size_t)B * Hn + C] = hprev;
    }
}

extern "C" void kernel_launch(void* const* d_in, const int* in_sizes, int n_in,
                              void* d_out, int out_size) {
    const float* x    = (const float*)d_in[0];
    const float* Wih0 = (const float*)d_in[1];
    const float* Whh0 = (const float*)d_in[2];
    const float* bh0  = (const float*)d_in[3];
    const float* Wax0 = (const float*)d_in[4];
    const float* Wah0 = (const float*)d_in[5];
    const float* ba0  = (const float*)d_in[6];
    const float* Wih1 = (const float*)d_in[7];
    const float* Whh1 = (const float*)d_in[8];
    const float* bh1  = (const float*)d_in[9];
    const float* Wax1 = (const float*)d_in[10];
    const float* Wah1 = (const float*)d_in[11];
    const float* ba1  = (const float*)d_in[12];
    float* out = (float*)d_out;

    const int smem = (KA * NCOL + KB * NCOL
                    + 2 * Hn * NBAT + Hn * NBAT
                    + 2 * 64 * RP
                    + 2 * NCOL) * 8;
    cudaFuncSetAttribute(rnn_kernel, cudaFuncAttributeMaxDynamicSharedMemorySize, smem);

    prep_kernel<<<Tn, PT>>>(x);
    rnn_kernel<<<GCTA, THREADS, smem>>>(
        Wih0, Whh0, bh0, Wax0, Wah0, ba0,
        Wih1, Whh1, bh1, Wax1, Wah1, ba1,
        out);
}